// round 1
// baseline (speedup 1.0000x reference)
#include <cuda_runtime.h>
#include <math.h>

#define LNUM   12
#define CDIM   768
#define HNUM   12
#define DHEAD  64
#define RF     64          // performer random features (M in reference)
#define NTOK   197
#define BATCH  32
#define TTOT   (BATCH*NTOK)     // 6304
#define NPATCH 196
#define PTOT   (BATCH*NPATCH)   // 6272
#define HIDD   3072
#define NCLS_  1000
#define QKVC   (3*CDIM)         // 2304

// ---------------- scratch (device globals; no allocs allowed) ----------------
__device__ float g_col  [PTOT*CDIM];
__device__ float g_patch[PTOT*CDIM];
__device__ float g_t    [TTOT*CDIM];
__device__ float g_ln   [TTOT*CDIM];
__device__ float g_qkv  [TTOT*QKVC];
__device__ float g_qp   [TTOT*CDIM];       // [t][h][m]
__device__ float g_kp   [TTOT*CDIM];       // holds dd-diag, then kp
__device__ float g_attn [TTOT*CDIM];
__device__ float g_hid  [TTOT*HIDD];
__device__ float g_kv   [BATCH*HNUM*RF*DHEAD];
__device__ float g_ks   [BATCH*HNUM*RF];
__device__ float g_lnf  [BATCH*CDIM];
__device__ int   g_stab;

// monotonic float<->int encoding for atomicMax over signed floats
__device__ __forceinline__ int   encf(float f){ int i=__float_as_int(f); return i<0 ? (i^0x7FFFFFFF) : i; }
__device__ __forceinline__ float decf(int i){ return __int_as_float(i<0 ? (i^0x7FFFFFFF) : i); }

// ---------------- im2col: x(32,3,224,224) -> col[6272][768] ------------------
__global__ void im2col_k(const float* __restrict__ x){
    int idx = blockIdx.x*blockDim.x + threadIdx.x;
    if (idx >= PTOT*CDIM) return;
    int p = idx / CDIM, j = idx % CDIM;
    int b = p / NPATCH, pin = p % NPATCH;
    int py = pin / 14, px = pin % 14;
    int ci = j >> 8, rem = j & 255;
    int ky = rem >> 4, kx = rem & 15;
    g_col[idx] = x[((b*3 + ci)*224 + (py*16+ky))*224 + (px*16+kx)];
}

// ---------------- assemble t = [cls|patch+b] + pos ---------------------------
__global__ void assemble_k(const float* __restrict__ cls, const float* __restrict__ pos){
    int idx = blockIdx.x*blockDim.x + threadIdx.x;
    if (idx >= TTOT*CDIM) return;
    int t = idx / CDIM, c = idx % CDIM;
    int b = t / NTOK, n = t % NTOK;
    float v = (n == 0) ? cls[c] : g_patch[(b*NPATCH + n - 1)*CDIM + c];
    g_t[idx] = v + pos[n*CDIM + c];
}

// ---------------- layernorm (block per row, 256 thr, C=768) ------------------
__global__ void ln_k(const float* __restrict__ in, long istride,
                     const float* __restrict__ w, const float* __restrict__ bb,
                     float* __restrict__ out){
    long row = blockIdx.x;
    const float* xr = in + row*istride;
    float* yr = out + row*(long)CDIM;
    int tid = threadIdx.x;
    float v0 = xr[tid], v1 = xr[tid+256], v2 = xr[tid+512];
    float s  = v0+v1+v2;
    float s2 = v0*v0 + v1*v1 + v2*v2;
    __shared__ float sh1[8], sh2[8], mv[2];
    #pragma unroll
    for (int o=16;o>0;o>>=1){
        s  += __shfl_down_sync(0xffffffffu, s,  o);
        s2 += __shfl_down_sync(0xffffffffu, s2, o);
    }
    if ((tid&31)==0){ sh1[tid>>5]=s; sh2[tid>>5]=s2; }
    __syncthreads();
    if (tid < 32){
        float a = (tid<8)? sh1[tid] : 0.f;
        float b2= (tid<8)? sh2[tid] : 0.f;
        #pragma unroll
        for (int o=4;o>0;o>>=1){
            a  += __shfl_down_sync(0xffffffffu, a,  o);
            b2 += __shfl_down_sync(0xffffffffu, b2, o);
        }
        if (tid==0){
            float mu = a * (1.f/CDIM);
            float var = b2 * (1.f/CDIM) - mu*mu;
            mv[0] = mu; mv[1] = rsqrtf(var + 1e-6f);
        }
    }
    __syncthreads();
    float mu = mv[0], rs = mv[1];
    yr[tid]     = (v0-mu)*rs*w[tid]     + bb[tid];
    yr[tid+256] = (v1-mu)*rs*w[tid+256] + bb[tid+256];
    yr[tid+512] = (v2-mu)*rs*w[tid+512] + bb[tid+512];
}

// ---------------- performer feature maps -------------------------------------
// phi for q: per (t,h) block of 64 threads; stab = per-row max
__global__ void phiq_k(const float* __restrict__ worf){
    int blk = blockIdx.x;
    int t = blk / HNUM, h = blk - t*HNUM;
    int m = threadIdx.x;
    __shared__ float dv[64];
    __shared__ float red[64];
    dv[m] = g_qkv[(long)t*QKVC + h*DHEAD + m];
    __syncthreads();
    red[m] = dv[m]; __syncthreads();
    #pragma unroll
    for (int o=32;o>0;o>>=1){ if (m<o) red[m]+=red[m+o]; __syncthreads(); }
    float diag = red[0] * 0.0625f;   // sum/2 * dn^2 = sum/16
    __syncthreads();
    float dot = 0.f;
    const float* wr = worf + m*DHEAD;
    #pragma unroll 16
    for (int d=0; d<DHEAD; d++) dot = fmaf(dv[d], wr[d], dot);
    red[m] = dot; __syncthreads();
    #pragma unroll
    for (int o=32;o>0;o>>=1){ if (m<o) red[m]=fmaxf(red[m],red[m+o]); __syncthreads(); }
    float stab = red[0];
    g_qp[(long)t*CDIM + h*DHEAD + m] = 0.35355339f*(expf(dot - diag - stab) + 1e-6f);
}

__global__ void reset_stab_k(){ g_stab = (int)0x80000000; }

// phi for k: store dd-diag, atomic global max of raw dd
__global__ void phik_k(const float* __restrict__ worf){
    int blk = blockIdx.x;
    int t = blk / HNUM, h = blk - t*HNUM;
    int m = threadIdx.x;
    __shared__ float dv[64];
    __shared__ float red[64];
    dv[m] = g_qkv[(long)t*QKVC + CDIM + h*DHEAD + m];
    __syncthreads();
    red[m] = dv[m]; __syncthreads();
    #pragma unroll
    for (int o=32;o>0;o>>=1){ if (m<o) red[m]+=red[m+o]; __syncthreads(); }
    float diag = red[0] * 0.0625f;
    __syncthreads();
    float dot = 0.f;
    const float* wr = worf + m*DHEAD;
    #pragma unroll 16
    for (int d=0; d<DHEAD; d++) dot = fmaf(dv[d], wr[d], dot);
    g_kp[(long)t*CDIM + h*DHEAD + m] = dot - diag;
    red[m] = dot; __syncthreads();
    #pragma unroll
    for (int o=32;o>0;o>>=1){ if (m<o) red[m]=fmaxf(red[m],red[m+o]); __syncthreads(); }
    if (m==0) atomicMax(&g_stab, encf(red[0]));
}

__global__ void kexp_k(){
    int idx = blockIdx.x*blockDim.x + threadIdx.x;
    if (idx >= TTOT*CDIM) return;
    float stab = decf(g_stab);
    g_kp[idx] = 0.35355339f*(expf(g_kp[idx] - stab) + 1e-6f);
}

// ---------------- kv[b,h,m,d] = sum_l kp*v ; ks = sum_l kp -------------------
__global__ void __launch_bounds__(256) kv_k(){
    int bh = blockIdx.x;
    int b = bh / HNUM, h = bh - b*HNUM;
    __shared__ float kps[64], vs[64];
    int tid = threadIdx.x;
    int m = tid >> 2, d0 = (tid & 3) * 16;
    float acc[16];
    #pragma unroll
    for (int j=0;j<16;j++) acc[j]=0.f;
    float ksacc = 0.f;
    for (int l=0; l<NTOK; l++){
        long t = (long)b*NTOK + l;
        if (tid < 64)        kps[tid]    = g_kp [t*CDIM + h*DHEAD + tid];
        else if (tid < 128)  vs[tid-64]  = g_qkv[t*QKVC + 2*CDIM + h*DHEAD + (tid-64)];
        __syncthreads();
        float km = kps[m];
        #pragma unroll
        for (int j=0;j<16;j++) acc[j] = fmaf(km, vs[d0+j], acc[j]);
        if (tid < 64) ksacc += kps[tid];
        __syncthreads();
    }
    #pragma unroll
    for (int j=0;j<16;j++) g_kv[((long)bh*RF + m)*DHEAD + d0 + j] = acc[j];
    if (tid < 64) g_ks[bh*RF + tid] = ksacc;
}

// ---------------- num = qp @ kv ; D = qp . ks ; attn = num/D -----------------
__global__ void __launch_bounds__(256) num_k(){
    int bh = blockIdx.x;
    int b = bh / HNUM, h = bh - b*HNUM;
    __shared__ float kvs[64][65];
    __shared__ float kss[64];
    int tid = threadIdx.x;
    for (int e=tid; e<RF*DHEAD; e+=256){
        kvs[e>>6][e&63] = g_kv[(long)bh*RF*DHEAD + e];
    }
    if (tid < 64) kss[tid] = g_ks[bh*RF + tid];
    __syncthreads();
    int grp = tid >> 6, d = tid & 63;
    for (int l=grp; l<NTOK; l+=4){
        long t = (long)b*NTOK + l;
        const float* qrow = &g_qp[t*CDIM + h*DHEAD];
        float num=0.f, den=0.f;
        #pragma unroll 16
        for (int mm=0; mm<RF; mm++){
            float qv = __ldg(qrow + mm);
            num = fmaf(qv, kvs[mm][d], num);
            den = fmaf(qv, kss[mm], den);
        }
        g_attn[t*CDIM + h*DHEAD + d] = num/den;
    }
}

// ---------------- generic NT GEMM: C = act(A @ W^T + bias) [+C] --------------
#define GBM 128
#define GBN 64
#define GBK 16

template<int ACT, bool RESID>
__global__ void __launch_bounds__(256) gemm_nt(
        const float* __restrict__ A, int lda,
        const float* __restrict__ W, int ldw,
        const float* __restrict__ bias,
        float* __restrict__ Cd, int ldc,
        int Mrows, int Ncols, int K)
{
    __shared__ float As[GBK][GBM+4];
    __shared__ float Ws[GBK][GBN+4];
    int tid = threadIdx.x;
    int tx = tid & 15, ty = tid >> 4;
    int row0 = blockIdx.y * GBM;
    int col0 = blockIdx.x * GBN;
    float acc[8][4];
    #pragma unroll
    for (int i=0;i<8;i++)
        #pragma unroll
        for (int j=0;j<4;j++) acc[i][j]=0.f;

    for (int k0=0; k0<K; k0+=GBK){
        #pragma unroll
        for (int it=0; it<8; it++){
            int e = tid + 256*it;
            int r = e >> 4, c = e & 15;
            int gr = row0 + r;
            As[c][r] = (gr < Mrows) ? A[(long)gr*lda + k0 + c] : 0.f;
        }
        #pragma unroll
        for (int it=0; it<4; it++){
            int e = tid + 256*it;
            int r = e >> 4, c = e & 15;
            int gn = col0 + r;
            Ws[c][r] = (gn < Ncols) ? W[(long)gn*ldw + k0 + c] : 0.f;
        }
        __syncthreads();
        #pragma unroll
        for (int kk=0; kk<GBK; kk++){
            float a[8], bv[4];
            #pragma unroll
            for (int i=0;i<8;i++) a[i] = As[kk][ty*8+i];
            #pragma unroll
            for (int j=0;j<4;j++) bv[j] = Ws[kk][tx*4+j];
            #pragma unroll
            for (int i=0;i<8;i++)
                #pragma unroll
                for (int j=0;j<4;j++)
                    acc[i][j] = fmaf(a[i], bv[j], acc[i][j]);
        }
        __syncthreads();
    }
    #pragma unroll
    for (int i=0;i<8;i++){
        int r = row0 + ty*8 + i;
        if (r >= Mrows) continue;
        #pragma unroll
        for (int j=0;j<4;j++){
            int c = col0 + tx*4 + j;
            if (c >= Ncols) continue;
            float v = acc[i][j] + bias[c];
            if (ACT == 1) v = v * normcdff(v);   // exact gelu: x*Phi(x)
            long o = (long)r*ldc + c;
            if (RESID) v += Cd[o];
            Cd[o] = v;
        }
    }
}

// ---------------- driver -----------------------------------------------------
extern "C" void kernel_launch(void* const* d_in, const int* in_sizes, int n_in,
                              void* d_out, int out_size){
    (void)in_sizes; (void)n_in; (void)out_size;
    const float* x       = (const float*)d_in[0];
    const float* patch_w = (const float*)d_in[1];
    const float* patch_b = (const float*)d_in[2];
    const float* cls     = (const float*)d_in[3];
    const float* pos     = (const float*)d_in[4];
    const float* ln1w    = (const float*)d_in[5];
    const float* ln1b    = (const float*)d_in[6];
    const float* qkvw    = (const float*)d_in[7];
    const float* qkvb    = (const float*)d_in[8];
    const float* worf    = (const float*)d_in[9];
    const float* projw   = (const float*)d_in[10];
    const float* projb   = (const float*)d_in[11];
    const float* ln2w    = (const float*)d_in[12];
    const float* ln2b    = (const float*)d_in[13];
    const float* fc1w    = (const float*)d_in[14];
    const float* fc1b    = (const float*)d_in[15];
    const float* fc2w    = (const float*)d_in[16];
    const float* fc2b    = (const float*)d_in[17];
    const float* lnfw    = (const float*)d_in[18];
    const float* lnfb    = (const float*)d_in[19];
    const float* headw   = (const float*)d_in[20];
    const float* headb   = (const float*)d_in[21];
    float* out = (float*)d_out;

    float *colp,*patchp,*tp,*lnp,*qkvp,*attnp,*hidp,*lnfp;
    cudaGetSymbolAddress((void**)&colp,  g_col);
    cudaGetSymbolAddress((void**)&patchp,g_patch);
    cudaGetSymbolAddress((void**)&tp,    g_t);
    cudaGetSymbolAddress((void**)&lnp,   g_ln);
    cudaGetSymbolAddress((void**)&qkvp,  g_qkv);
    cudaGetSymbolAddress((void**)&attnp, g_attn);
    cudaGetSymbolAddress((void**)&hidp,  g_hid);
    cudaGetSymbolAddress((void**)&lnfp,  g_lnf);

    const int gy_T = (TTOT + GBM - 1) / GBM;   // 50
    const int gy_P = (PTOT + GBM - 1) / GBM;   // 49

    // patch embedding as im2col + GEMM (bias = patch_b)
    im2col_k<<<(PTOT*CDIM+255)/256, 256>>>(x);
    gemm_nt<0,false><<<dim3(CDIM/GBN, gy_P), 256>>>(colp, CDIM, patch_w, CDIM, patch_b,
                                                    patchp, CDIM, PTOT, CDIM, CDIM);
    assemble_k<<<(TTOT*CDIM+255)/256, 256>>>(cls, pos);

    for (int i=0; i<LNUM; i++){
        ln_k<<<TTOT, 256>>>(tp, CDIM, ln1w + i*CDIM, ln1b + i*CDIM, lnp);
        gemm_nt<0,false><<<dim3(QKVC/GBN, gy_T), 256>>>(lnp, CDIM,
                qkvw + (long)i*QKVC*CDIM, CDIM, qkvb + i*QKVC,
                qkvp, QKVC, TTOT, QKVC, CDIM);
        phiq_k<<<TTOT*HNUM, 64>>>(worf + (long)i*RF*DHEAD);
        reset_stab_k<<<1,1>>>();
        phik_k<<<TTOT*HNUM, 64>>>(worf + (long)i*RF*DHEAD);
        kexp_k<<<(TTOT*CDIM+255)/256, 256>>>();
        kv_k<<<BATCH*HNUM, 256>>>();
        num_k<<<BATCH*HNUM, 256>>>();
        gemm_nt<0,true><<<dim3(CDIM/GBN, gy_T), 256>>>(attnp, CDIM,
                projw + (long)i*CDIM*CDIM, CDIM, projb + i*CDIM,
                tp, CDIM, TTOT, CDIM, CDIM);
        ln_k<<<TTOT, 256>>>(tp, CDIM, ln2w + i*CDIM, ln2b + i*CDIM, lnp);
        gemm_nt<1,false><<<dim3(HIDD/GBN, gy_T), 256>>>(lnp, CDIM,
                fc1w + (long)i*HIDD*CDIM, CDIM, fc1b + i*HIDD,
                hidp, HIDD, TTOT, HIDD, CDIM);
        gemm_nt<0,true><<<dim3(CDIM/GBN, gy_T), 256>>>(hidp, HIDD,
                fc2w + (long)i*CDIM*HIDD, HIDD, fc2b + i*CDIM,
                tp, CDIM, TTOT, CDIM, HIDD);
    }

    // final LN on cls tokens only (rows stride NTOK*CDIM), then head
    ln_k<<<BATCH, 256>>>(tp, (long)NTOK*CDIM, lnfw, lnfb, lnfp);
    gemm_nt<0,false><<<dim3((NCLS_+GBN-1)/GBN, 1), 256>>>(lnfp, CDIM, headw, CDIM, headb,
                                                          out, NCLS_, BATCH, NCLS_, CDIM);
}

// round 3
// speedup vs baseline: 1.2016x; 1.2016x over previous
#include <cuda_runtime.h>
#include <math.h>
#include <stdint.h>

#define LNUM   12
#define CDIM   768
#define HNUM   12
#define DHEAD  64
#define RF     64
#define NTOK   197
#define BATCH  32
#define TTOT   (BATCH*NTOK)     // 6304
#define NPATCH 196
#define PTOT   (BATCH*NPATCH)   // 6272
#define HIDD   3072
#define NCLS_  1000
#define QKVC   (3*CDIM)         // 2304

// ---------------- scratch (device globals; no allocs allowed) ----------------
__device__ float g_col  [PTOT*CDIM];
__device__ float g_patch[PTOT*CDIM];
__device__ float g_t    [TTOT*CDIM];
__device__ float g_ln   [TTOT*CDIM];
__device__ float g_qkv  [TTOT*QKVC];
__device__ float g_qp   [TTOT*CDIM];
__device__ float g_kp   [TTOT*CDIM];
__device__ float g_attn [TTOT*CDIM];
__device__ float g_hid  [TTOT*HIDD];
__device__ float g_kv   [BATCH*HNUM*RF*DHEAD];
__device__ float g_ks   [BATCH*HNUM*RF];
__device__ float g_lnf  [BATCH*CDIM];
__device__ int   g_stab;

__device__ __forceinline__ int   encf(float f){ int i=__float_as_int(f); return i<0 ? (i^0x7FFFFFFF) : i; }
__device__ __forceinline__ float decf(int i){ return __int_as_float(i<0 ? (i^0x7FFFFFFF) : i); }

// ---------------- im2col ----------------
__global__ void im2col_k(const float* __restrict__ x){
    int idx = blockIdx.x*blockDim.x + threadIdx.x;
    if (idx >= PTOT*CDIM) return;
    int p = idx / CDIM, j = idx % CDIM;
    int b = p / NPATCH, pin = p % NPATCH;
    int py = pin / 14, px = pin % 14;
    int ci = j >> 8, rem = j & 255;
    int ky = rem >> 4, kx = rem & 15;
    g_col[idx] = x[((b*3 + ci)*224 + (py*16+ky))*224 + (px*16+kx)];
}

// ---------------- assemble ----------------
__global__ void assemble_k(const float* __restrict__ cls, const float* __restrict__ pos){
    int idx = blockIdx.x*blockDim.x + threadIdx.x;
    if (idx >= TTOT*CDIM) return;
    int t = idx / CDIM, c = idx % CDIM;
    int b = t / NTOK, n = t % NTOK;
    float v = (n == 0) ? cls[c] : g_patch[(b*NPATCH + n - 1)*CDIM + c];
    g_t[idx] = v + pos[n*CDIM + c];
}

// ---------------- layernorm ----------------
__global__ void ln_k(const float* __restrict__ in, long istride,
                     const float* __restrict__ w, const float* __restrict__ bb,
                     float* __restrict__ out){
    long row = blockIdx.x;
    const float* xr = in + row*istride;
    float* yr = out + row*(long)CDIM;
    int tid = threadIdx.x;
    float v0 = xr[tid], v1 = xr[tid+256], v2 = xr[tid+512];
    float s  = v0+v1+v2;
    float s2 = v0*v0 + v1*v1 + v2*v2;
    __shared__ float sh1[8], sh2[8], mv[2];
    #pragma unroll
    for (int o=16;o>0;o>>=1){
        s  += __shfl_down_sync(0xffffffffu, s,  o);
        s2 += __shfl_down_sync(0xffffffffu, s2, o);
    }
    if ((tid&31)==0){ sh1[tid>>5]=s; sh2[tid>>5]=s2; }
    __syncthreads();
    if (tid < 32){
        float a = (tid<8)? sh1[tid] : 0.f;
        float b2= (tid<8)? sh2[tid] : 0.f;
        #pragma unroll
        for (int o=4;o>0;o>>=1){
            a  += __shfl_down_sync(0xffffffffu, a,  o);
            b2 += __shfl_down_sync(0xffffffffu, b2, o);
        }
        if (tid==0){
            float mu = a * (1.f/CDIM);
            float var = b2 * (1.f/CDIM) - mu*mu;
            mv[0] = mu; mv[1] = rsqrtf(var + 1e-6f);
        }
    }
    __syncthreads();
    float mu = mv[0], rs = mv[1];
    yr[tid]     = (v0-mu)*rs*w[tid]     + bb[tid];
    yr[tid+256] = (v1-mu)*rs*w[tid+256] + bb[tid+256];
    yr[tid+512] = (v2-mu)*rs*w[tid+512] + bb[tid+512];
}

// ---------------- performer feature maps ----------------
__global__ void phiq_k(const float* __restrict__ worf){
    int blk = blockIdx.x;
    int t = blk / HNUM, h = blk - t*HNUM;
    int m = threadIdx.x;
    __shared__ float dv[64];
    __shared__ float red[64];
    dv[m] = g_qkv[(long)t*QKVC + h*DHEAD + m];
    __syncthreads();
    red[m] = dv[m]; __syncthreads();
    #pragma unroll
    for (int o=32;o>0;o>>=1){ if (m<o) red[m]+=red[m+o]; __syncthreads(); }
    float diag = red[0] * 0.0625f;
    __syncthreads();
    float dot = 0.f;
    const float* wr = worf + m*DHEAD;
    #pragma unroll 16
    for (int d=0; d<DHEAD; d++) dot = fmaf(dv[d], wr[d], dot);
    red[m] = dot; __syncthreads();
    #pragma unroll
    for (int o=32;o>0;o>>=1){ if (m<o) red[m]=fmaxf(red[m],red[m+o]); __syncthreads(); }
    float stab = red[0];
    g_qp[(long)t*CDIM + h*DHEAD + m] = 0.35355339f*(expf(dot - diag - stab) + 1e-6f);
}

__global__ void reset_stab_k(){ g_stab = (int)0x80000000; }

__global__ void phik_k(const float* __restrict__ worf){
    int blk = blockIdx.x;
    int t = blk / HNUM, h = blk - t*HNUM;
    int m = threadIdx.x;
    __shared__ float dv[64];
    __shared__ float red[64];
    dv[m] = g_qkv[(long)t*QKVC + CDIM + h*DHEAD + m];
    __syncthreads();
    red[m] = dv[m]; __syncthreads();
    #pragma unroll
    for (int o=32;o>0;o>>=1){ if (m<o) red[m]+=red[m+o]; __syncthreads(); }
    float diag = red[0] * 0.0625f;
    __syncthreads();
    float dot = 0.f;
    const float* wr = worf + m*DHEAD;
    #pragma unroll 16
    for (int d=0; d<DHEAD; d++) dot = fmaf(dv[d], wr[d], dot);
    g_kp[(long)t*CDIM + h*DHEAD + m] = dot - diag;
    red[m] = dot; __syncthreads();
    #pragma unroll
    for (int o=32;o>0;o>>=1){ if (m<o) red[m]=fmaxf(red[m],red[m+o]); __syncthreads(); }
    if (m==0) atomicMax(&g_stab, encf(red[0]));
}

__global__ void kexp_k(){
    int idx = blockIdx.x*blockDim.x + threadIdx.x;
    if (idx >= TTOT*CDIM) return;
    float stab = decf(g_stab);
    g_kp[idx] = 0.35355339f*(expf(g_kp[idx] - stab) + 1e-6f);
}

// ---------------- kv / num ----------------
__global__ void __launch_bounds__(256) kv_k(){
    int bh = blockIdx.x;
    int b = bh / HNUM, h = bh - b*HNUM;
    __shared__ float kps[64], vs[64];
    int tid = threadIdx.x;
    int m = tid >> 2, d0 = (tid & 3) * 16;
    float acc[16];
    #pragma unroll
    for (int j=0;j<16;j++) acc[j]=0.f;
    float ksacc = 0.f;
    for (int l=0; l<NTOK; l++){
        long t = (long)b*NTOK + l;
        if (tid < 64)        kps[tid]    = g_kp [t*CDIM + h*DHEAD + tid];
        else if (tid < 128)  vs[tid-64]  = g_qkv[t*QKVC + 2*CDIM + h*DHEAD + (tid-64)];
        __syncthreads();
        float km = kps[m];
        #pragma unroll
        for (int j=0;j<16;j++) acc[j] = fmaf(km, vs[d0+j], acc[j]);
        if (tid < 64) ksacc += kps[tid];
        __syncthreads();
    }
    #pragma unroll
    for (int j=0;j<16;j++) g_kv[((long)bh*RF + m)*DHEAD + d0 + j] = acc[j];
    if (tid < 64) g_ks[bh*RF + tid] = ksacc;
}

__global__ void __launch_bounds__(256) num_k(){
    int bh = blockIdx.x;
    int b = bh / HNUM, h = bh - b*HNUM;
    __shared__ float kvs[64][65];
    __shared__ float kss[64];
    int tid = threadIdx.x;
    for (int e=tid; e<RF*DHEAD; e+=256){
        kvs[e>>6][e&63] = g_kv[(long)bh*RF*DHEAD + e];
    }
    if (tid < 64) kss[tid] = g_ks[bh*RF + tid];
    __syncthreads();
    int grp = tid >> 6, d = tid & 63;
    for (int l=grp; l<NTOK; l+=4){
        long t = (long)b*NTOK + l;
        const float* qrow = &g_qp[t*CDIM + h*DHEAD];
        float num=0.f, den=0.f;
        #pragma unroll 16
        for (int mm=0; mm<RF; mm++){
            float qv = __ldg(qrow + mm);
            num = fmaf(qv, kvs[mm][d], num);
            den = fmaf(qv, kss[mm], den);
        }
        g_attn[t*CDIM + h*DHEAD + d] = num/den;
    }
}

// ---------------- 3xTF32 tensor-core NT GEMM ----------------
// C = act(A @ W^T + bias) [+C],  A[M,K] row-major, W[N,K] row-major
// Each operand split v = hi + lo (both tf32); acc += ahi*blo + alo*bhi + ahi*bhi
#define TBM 128
#define TBN 128
#define TBK 16
#define SROW 20   // smem row stride (floats): conflict-free for frag lds & f4 st

__device__ __forceinline__ uint32_t f2tf(float f){
    uint32_t u; asm("cvt.rna.tf32.f32 %0, %1;" : "=r"(u) : "f"(f)); return u;
}
__device__ __forceinline__ void split_tf(float f, uint32_t& hi, uint32_t& lo){
    hi = f2tf(f);
    lo = f2tf(f - __uint_as_float(hi));
}

__device__ __forceinline__ void mma8(float* c, const uint32_t* a, const uint32_t* b){
    asm volatile("mma.sync.aligned.m16n8k8.row.col.f32.tf32.tf32.f32 "
        "{%0,%1,%2,%3}, {%4,%5,%6,%7}, {%8,%9}, {%0,%1,%2,%3};"
        : "+f"(c[0]), "+f"(c[1]), "+f"(c[2]), "+f"(c[3])
        : "r"(a[0]), "r"(a[1]), "r"(a[2]), "r"(a[3]), "r"(b[0]), "r"(b[1]));
}

template<int ACT, bool RESID>
__global__ void __launch_bounds__(256,1) gemm_tf32(
        const float* __restrict__ A, int lda,
        const float* __restrict__ W, int ldw,
        const float* __restrict__ bias,
        float* __restrict__ Cd, int ldc,
        int Mrows, int Ncols, int K)
{
    __shared__ uint32_t AsH[TBM*SROW];
    __shared__ uint32_t AsL[TBM*SROW];
    __shared__ uint32_t BsH[TBN*SROW];
    __shared__ uint32_t BsL[TBN*SROW];
    int tid  = threadIdx.x;
    int wid  = tid >> 5, lane = tid & 31;
    int wm   = (wid >> 2) * 64;
    int wn   = (wid & 3)  * 32;
    int row0 = blockIdx.y * TBM;
    int col0 = blockIdx.x * TBN;

    float acc[4][4][4];
    #pragma unroll
    for (int i=0;i<4;i++)
        #pragma unroll
        for (int j=0;j<4;j++)
            #pragma unroll
            for (int e=0;e<4;e++) acc[i][j][e]=0.f;

    int lm = tid >> 2;            // 0..63
    int lk = (tid & 3) * 4;       // 0,4,8,12
    const float* Ap0 = A + (long)(row0+lm   )*lda + lk;
    const float* Ap1 = A + (long)(row0+lm+64)*lda + lk;
    const float* Wp0 = W + (long)(col0+lm   )*ldw + lk;
    const float* Wp1 = W + (long)(col0+lm+64)*ldw + lk;
    bool va0 = (row0+lm    < Mrows);
    bool va1 = (row0+lm+64 < Mrows);
    bool vb0 = (col0+lm    < Ncols);
    bool vb1 = (col0+lm+64 < Ncols);

    float4 z4 = make_float4(0.f,0.f,0.f,0.f);
    float4 ra0 = va0 ? *(const float4*)Ap0 : z4;
    float4 ra1 = va1 ? *(const float4*)Ap1 : z4;
    float4 rb0 = vb0 ? *(const float4*)Wp0 : z4;
    float4 rb1 = vb1 ? *(const float4*)Wp1 : z4;

    for (int k0 = 0; k0 < K; k0 += TBK){
        {
            uint32_t h,l; int o;
            o = lm*SROW + lk;
            split_tf(ra0.x,h,l); AsH[o  ]=h; AsL[o  ]=l;
            split_tf(ra0.y,h,l); AsH[o+1]=h; AsL[o+1]=l;
            split_tf(ra0.z,h,l); AsH[o+2]=h; AsL[o+2]=l;
            split_tf(ra0.w,h,l); AsH[o+3]=h; AsL[o+3]=l;
            o = (lm+64)*SROW + lk;
            split_tf(ra1.x,h,l); AsH[o  ]=h; AsL[o  ]=l;
            split_tf(ra1.y,h,l); AsH[o+1]=h; AsL[o+1]=l;
            split_tf(ra1.z,h,l); AsH[o+2]=h; AsL[o+2]=l;
            split_tf(ra1.w,h,l); AsH[o+3]=h; AsL[o+3]=l;
            o = lm*SROW + lk;
            split_tf(rb0.x,h,l); BsH[o  ]=h; BsL[o  ]=l;
            split_tf(rb0.y,h,l); BsH[o+1]=h; BsL[o+1]=l;
            split_tf(rb0.z,h,l); BsH[o+2]=h; BsL[o+2]=l;
            split_tf(rb0.w,h,l); BsH[o+3]=h; BsL[o+3]=l;
            o = (lm+64)*SROW + lk;
            split_tf(rb1.x,h,l); BsH[o  ]=h; BsL[o  ]=l;
            split_tf(rb1.y,h,l); BsH[o+1]=h; BsL[o+1]=l;
            split_tf(rb1.z,h,l); BsH[o+2]=h; BsL[o+2]=l;
            split_tf(rb1.w,h,l); BsH[o+3]=h; BsL[o+3]=l;
        }
        __syncthreads();

        if (k0 + TBK < K){
            Ap0 += TBK; Ap1 += TBK; Wp0 += TBK; Wp1 += TBK;
            ra0 = va0 ? *(const float4*)Ap0 : z4;
            ra1 = va1 ? *(const float4*)Ap1 : z4;
            rb0 = vb0 ? *(const float4*)Wp0 : z4;
            rb1 = vb1 ? *(const float4*)Wp1 : z4;
        }

        #pragma unroll
        for (int ks=0; ks<2; ks++){
            int kk = ks*8 + (lane & 3);
            uint32_t afH[4][4], afL[4][4];
            #pragma unroll
            for (int mt=0; mt<4; mt++){
                int r = wm + mt*16 + (lane >> 2);
                int i0 =  r   *SROW + kk;
                int i1 = (r+8)*SROW + kk;
                afH[mt][0]=AsH[i0]; afH[mt][1]=AsH[i1]; afH[mt][2]=AsH[i0+4]; afH[mt][3]=AsH[i1+4];
                afL[mt][0]=AsL[i0]; afL[mt][1]=AsL[i1]; afL[mt][2]=AsL[i0+4]; afL[mt][3]=AsL[i1+4];
            }
            uint32_t bfH[4][2], bfL[4][2];
            #pragma unroll
            for (int nt=0; nt<4; nt++){
                int n = wn + nt*8 + (lane >> 2);
                int i0 = n*SROW + kk;
                bfH[nt][0]=BsH[i0]; bfH[nt][1]=BsH[i0+4];
                bfL[nt][0]=BsL[i0]; bfL[nt][1]=BsL[i0+4];
            }
            #pragma unroll
            for (int mt=0; mt<4; mt++)
                #pragma unroll
                for (int nt=0; nt<4; nt++){
                    mma8(acc[mt][nt], afH[mt], bfL[nt]);
                    mma8(acc[mt][nt], afL[mt], bfH[nt]);
                    mma8(acc[mt][nt], afH[mt], bfH[nt]);
                }
        }
        __syncthreads();
    }

    // epilogue
    #pragma unroll
    for (int mt=0; mt<4; mt++){
        int r0 = row0 + wm + mt*16 + (lane >> 2);
        #pragma unroll
        for (int nt=0; nt<4; nt++){
            int c0 = col0 + wn + nt*8 + (lane & 3)*2;
            #pragma unroll
            for (int e=0; e<4; e++){
                int r = r0 + (e>>1)*8;
                int c = c0 + (e&1);
                if (r >= Mrows || c >= Ncols) continue;
                float v = acc[mt][nt][e] + bias[c];
                if (ACT == 1) v = v * normcdff(v);
                long o = (long)r*ldc + c;
                if (RESID) v += Cd[o];
                Cd[o] = v;
            }
        }
    }
}

// ---------------- driver ----------------
extern "C" void kernel_launch(void* const* d_in, const int* in_sizes, int n_in,
                              void* d_out, int out_size){
    (void)in_sizes; (void)n_in; (void)out_size;
    const float* x       = (const float*)d_in[0];
    const float* patch_w = (const float*)d_in[1];
    const float* patch_b = (const float*)d_in[2];
    const float* cls     = (const float*)d_in[3];
    const float* pos     = (const float*)d_in[4];
    const float* ln1w    = (const float*)d_in[5];
    const float* ln1b    = (const float*)d_in[6];
    const float* qkvw    = (const float*)d_in[7];
    const float* qkvb    = (const float*)d_in[8];
    const float* worf    = (const float*)d_in[9];
    const float* projw   = (const float*)d_in[10];
    const float* projb   = (const float*)d_in[11];
    const float* ln2w    = (const float*)d_in[12];
    const float* ln2b    = (const float*)d_in[13];
    const float* fc1w    = (const float*)d_in[14];
    const float* fc1b    = (const float*)d_in[15];
    const float* fc2w    = (const float*)d_in[16];
    const float* fc2b    = (const float*)d_in[17];
    const float* lnfw    = (const float*)d_in[18];
    const float* lnfb    = (const float*)d_in[19];
    const float* headw   = (const float*)d_in[20];
    const float* headb   = (const float*)d_in[21];
    float* out = (float*)d_out;

    float *colp,*patchp,*tp,*lnp,*qkvp,*attnp,*hidp,*lnfp;
    cudaGetSymbolAddress((void**)&colp,  g_col);
    cudaGetSymbolAddress((void**)&patchp,g_patch);
    cudaGetSymbolAddress((void**)&tp,    g_t);
    cudaGetSymbolAddress((void**)&lnp,   g_ln);
    cudaGetSymbolAddress((void**)&qkvp,  g_qkv);
    cudaGetSymbolAddress((void**)&attnp, g_attn);
    cudaGetSymbolAddress((void**)&hidp,  g_hid);
    cudaGetSymbolAddress((void**)&lnfp,  g_lnf);

    const int gyT = (TTOT + TBM - 1) / TBM;    // 50
    const int gyP = (PTOT + TBM - 1) / TBM;    // 49

    im2col_k<<<(PTOT*CDIM+255)/256, 256>>>(x);
    gemm_tf32<0,false><<<dim3(CDIM/TBN, gyP), 256>>>(colp, CDIM, patch_w, CDIM, patch_b,
                                                     patchp, CDIM, PTOT, CDIM, CDIM);
    assemble_k<<<(TTOT*CDIM+255)/256, 256>>>(cls, pos);

    for (int i=0; i<LNUM; i++){
        ln_k<<<TTOT, 256>>>(tp, CDIM, ln1w + i*CDIM, ln1b + i*CDIM, lnp);
        gemm_tf32<0,false><<<dim3(QKVC/TBN, gyT), 256>>>(lnp, CDIM,
                qkvw + (long)i*QKVC*CDIM, CDIM, qkvb + i*QKVC,
                qkvp, QKVC, TTOT, QKVC, CDIM);
        phiq_k<<<TTOT*HNUM, 64>>>(worf + (long)i*RF*DHEAD);
        reset_stab_k<<<1,1>>>();
        phik_k<<<TTOT*HNUM, 64>>>(worf + (long)i*RF*DHEAD);
        kexp_k<<<(TTOT*CDIM+255)/256, 256>>>();
        kv_k<<<BATCH*HNUM, 256>>>();
        num_k<<<BATCH*HNUM, 256>>>();
        gemm_tf32<0,true><<<dim3(CDIM/TBN, gyT), 256>>>(attnp, CDIM,
                projw + (long)i*CDIM*CDIM, CDIM, projb + i*CDIM,
                tp, CDIM, TTOT, CDIM, CDIM);
        ln_k<<<TTOT, 256>>>(tp, CDIM, ln2w + i*CDIM, ln2b + i*CDIM, lnp);
        gemm_tf32<1,false><<<dim3(HIDD/TBN, gyT), 256>>>(lnp, CDIM,
                fc1w + (long)i*HIDD*CDIM, CDIM, fc1b + i*HIDD,
                hidp, HIDD, TTOT, HIDD, CDIM);
        gemm_tf32<0,true><<<dim3(CDIM/TBN, gyT), 256>>>(hidp, HIDD,
                fc2w + (long)i*CDIM*HIDD, HIDD, fc2b + i*CDIM,
                tp, CDIM, TTOT, CDIM, HIDD);
    }

    ln_k<<<BATCH, 256>>>(tp, (long)NTOK*CDIM, lnfw, lnfb, lnfp);
    gemm_tf32<0,false><<<dim3((NCLS_+TBN-1)/TBN, 1), 256>>>(lnfp, CDIM, headw, CDIM, headb,
                                                            out, NCLS_, BATCH, NCLS_, CDIM);
}

// round 5
// speedup vs baseline: 1.6406x; 1.3654x over previous
#include <cuda_runtime.h>
#include <cuda_bf16.h>
#include <math.h>
#include <stdint.h>

#define LNUM   12
#define CDIM   768
#define HNUM   12
#define DHEAD  64
#define RF     64
#define NTOK   197
#define BATCH  32
#define TTOT   (BATCH*NTOK)     // 6304
#define NPATCH 196
#define PTOT   (BATCH*NPATCH)   // 6272
#define HIDD   3072
#define NCLS_  1000
#define QKVC   (3*CDIM)         // 2304

// weight split buffer offsets (elements)
#define WOFF_PATCH 0
#define WOFF_QKV   589824
#define WOFF_PROJ  21823488
#define WOFF_FC1   28901376
#define WOFF_FC2   57212928
#define WOFF_HEAD  85524480
#define WTOT       86292480

// ---------------- scratch (device globals; no allocs allowed) ----------------
__device__ float g_col  [PTOT*CDIM];
__device__ float g_patch[PTOT*CDIM];
__device__ float g_t    [TTOT*CDIM];
__device__ float g_ln   [TTOT*CDIM];
__device__ float g_qkv  [TTOT*QKVC];
__device__ float g_qp   [TTOT*CDIM];
__device__ float g_kp   [TTOT*CDIM];
__device__ float g_attn [TTOT*CDIM];
__device__ float g_hid  [TTOT*HIDD];
__device__ float g_kv   [BATCH*HNUM*RF*DHEAD];
__device__ float g_ks   [BATCH*HNUM*RF];
__device__ float g_lnf  [BATCH*CDIM];
__device__ int   g_stab;
__device__ __nv_bfloat16 g_wh[WTOT];
__device__ __nv_bfloat16 g_wl[WTOT];

__device__ __forceinline__ int   encf(float f){ int i=__float_as_int(f); return i<0 ? (i^0x7FFFFFFF) : i; }
__device__ __forceinline__ float decf(int i){ return __int_as_float(i<0 ? (i^0x7FFFFFFF) : i); }

// ---------------- weight split: fp32 -> bf16 hi + bf16 lo ----------------
__global__ void wsplit4_k(const float* __restrict__ w,
                          __nv_bfloat16* __restrict__ hi,
                          __nv_bfloat16* __restrict__ lo, int n4){
    int i = blockIdx.x*blockDim.x + threadIdx.x;
    if (i >= n4) return;
    float4 v = ((const float4*)w)[i];
    __nv_bfloat16 hx = __float2bfloat16(v.x);
    __nv_bfloat16 hy = __float2bfloat16(v.y);
    __nv_bfloat16 hz = __float2bfloat16(v.z);
    __nv_bfloat16 hw = __float2bfloat16(v.w);
    __nv_bfloat162* h2 = (__nv_bfloat162*)hi;
    __nv_bfloat162* l2 = (__nv_bfloat162*)lo;
    h2[i*2]   = __halves2bfloat162(hx, hy);
    h2[i*2+1] = __halves2bfloat162(hz, hw);
    l2[i*2]   = __halves2bfloat162(__float2bfloat16(v.x - __bfloat162float(hx)),
                                   __float2bfloat16(v.y - __bfloat162float(hy)));
    l2[i*2+1] = __halves2bfloat162(__float2bfloat16(v.z - __bfloat162float(hz)),
                                   __float2bfloat16(v.w - __bfloat162float(hw)));
}

// ---------------- im2col ----------------
__global__ void im2col_k(const float* __restrict__ x){
    int idx = blockIdx.x*blockDim.x + threadIdx.x;
    if (idx >= PTOT*CDIM) return;
    int p = idx / CDIM, j = idx % CDIM;
    int b = p / NPATCH, pin = p % NPATCH;
    int py = pin / 14, px = pin % 14;
    int ci = j >> 8, rem = j & 255;
    int ky = rem >> 4, kx = rem & 15;
    g_col[idx] = x[((b*3 + ci)*224 + (py*16+ky))*224 + (px*16+kx)];
}

// ---------------- assemble ----------------
__global__ void assemble_k(const float* __restrict__ cls, const float* __restrict__ pos){
    int idx = blockIdx.x*blockDim.x + threadIdx.x;
    if (idx >= TTOT*CDIM) return;
    int t = idx / CDIM, c = idx % CDIM;
    int b = t / NTOK, n = t % NTOK;
    float v = (n == 0) ? cls[c] : g_patch[(b*NPATCH + n - 1)*CDIM + c];
    g_t[idx] = v + pos[n*CDIM + c];
}

// ---------------- layernorm ----------------
__global__ void ln_k(const float* __restrict__ in, long istride,
                     const float* __restrict__ w, const float* __restrict__ bb,
                     float* __restrict__ out){
    long row = blockIdx.x;
    const float* xr = in + row*istride;
    float* yr = out + row*(long)CDIM;
    int tid = threadIdx.x;
    float v0 = xr[tid], v1 = xr[tid+256], v2 = xr[tid+512];
    float s  = v0+v1+v2;
    float s2 = v0*v0 + v1*v1 + v2*v2;
    __shared__ float sh1[8], sh2[8], mv[2];
    #pragma unroll
    for (int o=16;o>0;o>>=1){
        s  += __shfl_down_sync(0xffffffffu, s,  o);
        s2 += __shfl_down_sync(0xffffffffu, s2, o);
    }
    if ((tid&31)==0){ sh1[tid>>5]=s; sh2[tid>>5]=s2; }
    __syncthreads();
    if (tid < 32){
        float a = (tid<8)? sh1[tid] : 0.f;
        float b2= (tid<8)? sh2[tid] : 0.f;
        #pragma unroll
        for (int o=4;o>0;o>>=1){
            a  += __shfl_down_sync(0xffffffffu, a,  o);
            b2 += __shfl_down_sync(0xffffffffu, b2, o);
        }
        if (tid==0){
            float mu = a * (1.f/CDIM);
            float var = b2 * (1.f/CDIM) - mu*mu;
            mv[0] = mu; mv[1] = rsqrtf(var + 1e-6f);
        }
    }
    __syncthreads();
    float mu = mv[0], rs = mv[1];
    yr[tid]     = (v0-mu)*rs*w[tid]     + bb[tid];
    yr[tid+256] = (v1-mu)*rs*w[tid+256] + bb[tid+256];
    yr[tid+512] = (v2-mu)*rs*w[tid+512] + bb[tid+512];
}

// ---------------- performer feature maps ----------------
__global__ void phiq_k(const float* __restrict__ worf){
    int blk = blockIdx.x;
    int t = blk / HNUM, h = blk - t*HNUM;
    int m = threadIdx.x;
    __shared__ float dv[64];
    __shared__ float red[64];
    dv[m] = g_qkv[(long)t*QKVC + h*DHEAD + m];
    __syncthreads();
    red[m] = dv[m]; __syncthreads();
    #pragma unroll
    for (int o=32;o>0;o>>=1){ if (m<o) red[m]+=red[m+o]; __syncthreads(); }
    float diag = red[0] * 0.0625f;
    __syncthreads();
    float dot = 0.f;
    const float* wr = worf + m*DHEAD;
    #pragma unroll 16
    for (int d=0; d<DHEAD; d++) dot = fmaf(dv[d], wr[d], dot);
    red[m] = dot; __syncthreads();
    #pragma unroll
    for (int o=32;o>0;o>>=1){ if (m<o) red[m]=fmaxf(red[m],red[m+o]); __syncthreads(); }
    float stab = red[0];
    g_qp[(long)t*CDIM + h*DHEAD + m] = 0.35355339f*(expf(dot - diag - stab) + 1e-6f);
}

__global__ void reset_stab_k(){ g_stab = (int)0x80000000; }

__global__ void phik_k(const float* __restrict__ worf){
    int blk = blockIdx.x;
    int t = blk / HNUM, h = blk - t*HNUM;
    int m = threadIdx.x;
    __shared__ float dv[64];
    __shared__ float red[64];
    dv[m] = g_qkv[(long)t*QKVC + CDIM + h*DHEAD + m];
    __syncthreads();
    red[m] = dv[m]; __syncthreads();
    #pragma unroll
    for (int o=32;o>0;o>>=1){ if (m<o) red[m]+=red[m+o]; __syncthreads(); }
    float diag = red[0] * 0.0625f;
    __syncthreads();
    float dot = 0.f;
    const float* wr = worf + m*DHEAD;
    #pragma unroll 16
    for (int d=0; d<DHEAD; d++) dot = fmaf(dv[d], wr[d], dot);
    g_kp[(long)t*CDIM + h*DHEAD + m] = dot - diag;
    red[m] = dot; __syncthreads();
    #pragma unroll
    for (int o=32;o>0;o>>=1){ if (m<o) red[m]=fmaxf(red[m],red[m+o]); __syncthreads(); }
    if (m==0) atomicMax(&g_stab, encf(red[0]));
}

__global__ void kexp_k(){
    int idx = blockIdx.x*blockDim.x + threadIdx.x;
    if (idx >= TTOT*CDIM) return;
    float stab = decf(g_stab);
    g_kp[idx] = 0.35355339f*(expf(g_kp[idx] - stab) + 1e-6f);
}

// ---------------- kv / num ----------------
__global__ void __launch_bounds__(256) kv_k(){
    int bh = blockIdx.x;
    int b = bh / HNUM, h = bh - b*HNUM;
    __shared__ float kps[64], vs[64];
    int tid = threadIdx.x;
    int m = tid >> 2, d0 = (tid & 3) * 16;
    float acc[16];
    #pragma unroll
    for (int j=0;j<16;j++) acc[j]=0.f;
    float ksacc = 0.f;
    for (int l=0; l<NTOK; l++){
        long t = (long)b*NTOK + l;
        if (tid < 64)        kps[tid]    = g_kp [t*CDIM + h*DHEAD + tid];
        else if (tid < 128)  vs[tid-64]  = g_qkv[t*QKVC + 2*CDIM + h*DHEAD + (tid-64)];
        __syncthreads();
        float km = kps[m];
        #pragma unroll
        for (int j=0;j<16;j++) acc[j] = fmaf(km, vs[d0+j], acc[j]);
        if (tid < 64) ksacc += kps[tid];
        __syncthreads();
    }
    #pragma unroll
    for (int j=0;j<16;j++) g_kv[((long)bh*RF + m)*DHEAD + d0 + j] = acc[j];
    if (tid < 64) g_ks[bh*RF + tid] = ksacc;
}

__global__ void __launch_bounds__(256) num_k(){
    int bh = blockIdx.x;
    int b = bh / HNUM, h = bh - b*HNUM;
    __shared__ float kvs[64][65];
    __shared__ float kss[64];
    int tid = threadIdx.x;
    for (int e=tid; e<RF*DHEAD; e+=256){
        kvs[e>>6][e&63] = g_kv[(long)bh*RF*DHEAD + e];
    }
    if (tid < 64) kss[tid] = g_ks[bh*RF + tid];
    __syncthreads();
    int grp = tid >> 6, d = tid & 63;
    for (int l=grp; l<NTOK; l+=4){
        long t = (long)b*NTOK + l;
        const float* qrow = &g_qp[t*CDIM + h*DHEAD];
        float num=0.f, den=0.f;
        #pragma unroll 16
        for (int mm=0; mm<RF; mm++){
            float qv = __ldg(qrow + mm);
            num = fmaf(qv, kvs[mm][d], num);
            den = fmaf(qv, kss[mm], den);
        }
        g_attn[t*CDIM + h*DHEAD + d] = num/den;
    }
}

// ---------------- bf16-split tensor-core NT GEMM ----------------
// C = act(A @ W^T + bias) [+C]; A[M,K] fp32 row-major; W pre-split bf16 hi/lo [N,K].
// acc += Ah*Bh + Ah*Bl + Al*Bh  (fp32 accumulate)
// CTA tile 128x128, K-chunk 32. SMEM u32 = 2 bf16 (k-pair), SROW=20 conflict-free.
#define SROW 20

__device__ __forceinline__ void split2(float a, float b, uint32_t& hi, uint32_t& lo){
    __nv_bfloat16 ha = __float2bfloat16(a);
    __nv_bfloat16 hb = __float2bfloat16(b);
    float ra = a - __bfloat162float(ha);
    float rb = b - __bfloat162float(hb);
    __nv_bfloat162 H = __halves2bfloat162(ha, hb);
    __nv_bfloat162 L = __halves2bfloat162(__float2bfloat16(ra), __float2bfloat16(rb));
    hi = *reinterpret_cast<uint32_t*>(&H);
    lo = *reinterpret_cast<uint32_t*>(&L);
}

__device__ __forceinline__ void mma16(float* c, const uint32_t* a, const uint32_t* b){
    asm volatile("mma.sync.aligned.m16n8k16.row.col.f32.bf16.bf16.f32 "
        "{%0,%1,%2,%3}, {%4,%5,%6,%7}, {%8,%9}, {%0,%1,%2,%3};"
        : "+f"(c[0]), "+f"(c[1]), "+f"(c[2]), "+f"(c[3])
        : "r"(a[0]), "r"(a[1]), "r"(a[2]), "r"(a[3]), "r"(b[0]), "r"(b[1]));
}

template<int ACT, bool RESID>
__global__ void __launch_bounds__(256,2) gemm_bf(
        const float* __restrict__ A, int lda,
        const __nv_bfloat16* __restrict__ Wh,
        const __nv_bfloat16* __restrict__ Wl, int ldw,
        const float* __restrict__ bias,
        float* __restrict__ Cd, int ldc,
        int Mrows, int Ncols, int K)
{
    extern __shared__ uint32_t sm[];
    uint32_t* AsH = sm;
    uint32_t* AsL = sm + 2560;
    uint32_t* BsH = sm + 5120;
    uint32_t* BsL = sm + 7680;

    int tid  = threadIdx.x;
    int wid  = tid >> 5, lane = tid & 31;
    int wm   = (wid >> 2) * 64;
    int wn   = (wid & 3)  * 32;
    int row0 = blockIdx.y * 128;
    int col0 = blockIdx.x * 128;

    float acc[4][4][4];
    #pragma unroll
    for (int i=0;i<4;i++)
        #pragma unroll
        for (int j=0;j<4;j++)
            #pragma unroll
            for (int e=0;e<4;e++) acc[i][j][e]=0.f;

    // A staging indices: e = tid+256*it -> r=e>>3 (0..127), kq=e&7 (float4 within 32)
    // B staging indices: e = tid+256*it -> r=e>>2 (0..127), cc=e&3 (16B chunk of 32 bf16)
    for (int k0 = 0; k0 < K; k0 += 32){
        #pragma unroll
        for (int it = 0; it < 4; it++){
            int e = tid + 256*it;
            int r = e >> 3, kq = e & 7;
            int gr = row0 + r;
            float4 v = make_float4(0.f,0.f,0.f,0.f);
            if (gr < Mrows) v = *(const float4*)(A + (long)gr*lda + k0 + kq*4);
            uint32_t h0,l0,h1,l1;
            split2(v.x, v.y, h0, l0);
            split2(v.z, v.w, h1, l1);
            int o = r*SROW + kq*2;
            AsH[o] = h0; AsH[o+1] = h1;
            AsL[o] = l0; AsL[o+1] = l1;
        }
        #pragma unroll
        for (int it = 0; it < 2; it++){
            int e = tid + 256*it;
            int r = e >> 2, cc = e & 3;
            int gn = col0 + r;
            uint4 vh = make_uint4(0u,0u,0u,0u);
            uint4 vl = make_uint4(0u,0u,0u,0u);
            if (gn < Ncols){
                vh = *(const uint4*)(Wh + (long)gn*ldw + k0 + cc*8);
                vl = *(const uint4*)(Wl + (long)gn*ldw + k0 + cc*8);
            }
            int o = r*SROW + cc*4;
            *(uint4*)&BsH[o] = vh;
            *(uint4*)&BsL[o] = vl;
        }
        __syncthreads();

        #pragma unroll
        for (int ks = 0; ks < 2; ks++){
            int kk = ks*8 + (lane & 3);
            uint32_t bH[4][2], bL[4][2];
            #pragma unroll
            for (int nt = 0; nt < 4; nt++){
                int n = wn + nt*8 + (lane >> 2);
                int o = n*SROW + kk;
                bH[nt][0] = BsH[o]; bH[nt][1] = BsH[o+4];
                bL[nt][0] = BsL[o]; bL[nt][1] = BsL[o+4];
            }
            #pragma unroll
            for (int mt = 0; mt < 4; mt++){
                int r = wm + mt*16 + (lane >> 2);
                int o0 =  r   *SROW + kk;
                int o1 = (r+8)*SROW + kk;
                uint32_t aH[4] = { AsH[o0], AsH[o1], AsH[o0+4], AsH[o1+4] };
                uint32_t aL[4] = { AsL[o0], AsL[o1], AsL[o0+4], AsL[o1+4] };
                #pragma unroll
                for (int nt = 0; nt < 4; nt++){
                    mma16(acc[mt][nt], aH, bH[nt]);
                    mma16(acc[mt][nt], aH, bL[nt]);
                    mma16(acc[mt][nt], aL, bH[nt]);
                }
            }
        }
        __syncthreads();
    }

    // epilogue
    #pragma unroll
    for (int mt=0; mt<4; mt++){
        int r0 = row0 + wm + mt*16 + (lane >> 2);
        #pragma unroll
        for (int nt=0; nt<4; nt++){
            int c0 = col0 + wn + nt*8 + (lane & 3)*2;
            #pragma unroll
            for (int e=0; e<4; e++){
                int r = r0 + (e>>1)*8;
                int c = c0 + (e&1);
                if (r >= Mrows || c >= Ncols) continue;
                float v = acc[mt][nt][e] + bias[c];
                if (ACT == 1) v = v * normcdff(v);
                long o = (long)r*ldc + c;
                if (RESID) v += Cd[o];
                Cd[o] = v;
            }
        }
    }
}

// ---------------- driver ----------------
extern "C" void kernel_launch(void* const* d_in, const int* in_sizes, int n_in,
                              void* d_out, int out_size){
    (void)in_sizes; (void)n_in; (void)out_size;
    const float* x       = (const float*)d_in[0];
    const float* patch_w = (const float*)d_in[1];
    const float* patch_b = (const float*)d_in[2];
    const float* cls     = (const float*)d_in[3];
    const float* pos     = (const float*)d_in[4];
    const float* ln1w    = (const float*)d_in[5];
    const float* ln1b    = (const float*)d_in[6];
    const float* qkvw    = (const float*)d_in[7];
    const float* qkvb    = (const float*)d_in[8];
    const float* worf    = (const float*)d_in[9];
    const float* projw   = (const float*)d_in[10];
    const float* projb   = (const float*)d_in[11];
    const float* ln2w    = (const float*)d_in[12];
    const float* ln2b    = (const float*)d_in[13];
    const float* fc1w    = (const float*)d_in[14];
    const float* fc1b    = (const float*)d_in[15];
    const float* fc2w    = (const float*)d_in[16];
    const float* fc2b    = (const float*)d_in[17];
    const float* lnfw    = (const float*)d_in[18];
    const float* lnfb    = (const float*)d_in[19];
    const float* headw   = (const float*)d_in[20];
    const float* headb   = (const float*)d_in[21];
    float* out = (float*)d_out;

    float *colp,*patchp,*tp,*lnp,*qkvp,*attnp,*hidp,*lnfp;
    __nv_bfloat16 *whp, *wlp;
    cudaGetSymbolAddress((void**)&colp,  g_col);
    cudaGetSymbolAddress((void**)&patchp,g_patch);
    cudaGetSymbolAddress((void**)&tp,    g_t);
    cudaGetSymbolAddress((void**)&lnp,   g_ln);
    cudaGetSymbolAddress((void**)&qkvp,  g_qkv);
    cudaGetSymbolAddress((void**)&attnp, g_attn);
    cudaGetSymbolAddress((void**)&hidp,  g_hid);
    cudaGetSymbolAddress((void**)&lnfp,  g_lnf);
    cudaGetSymbolAddress((void**)&whp,   g_wh);
    cudaGetSymbolAddress((void**)&wlp,   g_wl);

    const int SMB = 10240 * 4;   // 40KB dynamic smem

    // ---- weight pre-split (once per launch) ----
    {
        auto ws = [&](const float* src, long off, long cnt){
            wsplit4_k<<<(int)((cnt/4 + 255)/256), 256>>>(src, whp+off, wlp+off, (int)(cnt/4));
        };
        ws(patch_w, WOFF_PATCH, 589824);
        ws(headw,   WOFF_HEAD,  768000);
        for (int i=0;i<LNUM;i++){
            ws(qkvw  + (long)i*QKVC*CDIM, WOFF_QKV  + (long)i*1769472, 1769472);
            ws(projw + (long)i*CDIM*CDIM, WOFF_PROJ + (long)i*589824,  589824);
            ws(fc1w  + (long)i*HIDD*CDIM, WOFF_FC1  + (long)i*2359296, 2359296);
            ws(fc2w  + (long)i*CDIM*HIDD, WOFF_FC2  + (long)i*2359296, 2359296);
        }
    }

    const int mtT = (TTOT + 127) / 128;   // 50
    const int mtP = (PTOT + 127) / 128;   // 49

    im2col_k<<<(PTOT*CDIM+255)/256, 256>>>(x);
    gemm_bf<0,false><<<dim3(CDIM/128, mtP), 256, SMB>>>(colp, CDIM,
            whp+WOFF_PATCH, wlp+WOFF_PATCH, CDIM, patch_b,
            patchp, CDIM, PTOT, CDIM, CDIM);
    assemble_k<<<(TTOT*CDIM+255)/256, 256>>>(cls, pos);

    for (int i=0; i<LNUM; i++){
        ln_k<<<TTOT, 256>>>(tp, CDIM, ln1w + i*CDIM, ln1b + i*CDIM, lnp);
        gemm_bf<0,false><<<dim3(QKVC/128, mtT), 256, SMB>>>(lnp, CDIM,
                whp+WOFF_QKV+(long)i*1769472, wlp+WOFF_QKV+(long)i*1769472, CDIM,
                qkvb + i*QKVC, qkvp, QKVC, TTOT, QKVC, CDIM);
        phiq_k<<<TTOT*HNUM, 64>>>(worf + (long)i*RF*DHEAD);
        reset_stab_k<<<1,1>>>();
        phik_k<<<TTOT*HNUM, 64>>>(worf + (long)i*RF*DHEAD);
        kexp_k<<<(TTOT*CDIM+255)/256, 256>>>();
        kv_k<<<BATCH*HNUM, 256>>>();
        num_k<<<BATCH*HNUM, 256>>>();
        gemm_bf<0,true><<<dim3(CDIM/128, mtT), 256, SMB>>>(attnp, CDIM,
                whp+WOFF_PROJ+(long)i*589824, wlp+WOFF_PROJ+(long)i*589824, CDIM,
                projb + i*CDIM, tp, CDIM, TTOT, CDIM, CDIM);
        ln_k<<<TTOT, 256>>>(tp, CDIM, ln2w + i*CDIM, ln2b + i*CDIM, lnp);
        gemm_bf<1,false><<<dim3(HIDD/128, mtT), 256, SMB>>>(lnp, CDIM,
                whp+WOFF_FC1+(long)i*2359296, wlp+WOFF_FC1+(long)i*2359296, CDIM,
                fc1b + i*HIDD, hidp, HIDD, TTOT, HIDD, CDIM);
        gemm_bf<0,true><<<dim3(CDIM/128, mtT), 256, SMB>>>(hidp, HIDD,
                whp+WOFF_FC2+(long)i*2359296, wlp+WOFF_FC2+(long)i*2359296, HIDD,
                fc2b + i*CDIM, tp, CDIM, TTOT, CDIM, HIDD);
    }

    ln_k<<<BATCH, 256>>>(tp, (long)NTOK*CDIM, lnfw, lnfb, lnfp);
    gemm_bf<0,false><<<dim3((NCLS_+127)/128, 1), 256, SMB>>>(lnfp, CDIM,
            whp+WOFF_HEAD, wlp+WOFF_HEAD, CDIM, headb,
            out, NCLS_, BATCH, NCLS_, CDIM);
}

// round 6
// speedup vs baseline: 1.6671x; 1.0162x over previous
#include <cuda_runtime.h>
#include <cuda_bf16.h>
#include <math.h>
#include <stdint.h>

#define LNUM   12
#define CDIM   768
#define HNUM   12
#define DHEAD  64
#define RF     64
#define NTOK   197
#define BATCH  32
#define TTOT   (BATCH*NTOK)     // 6304
#define NPATCH 196
#define PTOT   (BATCH*NPATCH)   // 6272
#define HIDD   3072
#define NCLS_  1000
#define QKVC   (3*CDIM)         // 2304

// weight split buffer offsets (elements)
#define WOFF_PATCH 0
#define WOFF_QKV   589824
#define WOFF_PROJ  21823488
#define WOFF_FC1   28901376
#define WOFF_FC2   57212928
#define WOFF_HEAD  85524480
#define WTOT       86292480

// ---------------- scratch (device globals; no allocs allowed) ----------------
__device__ float g_patch[PTOT*CDIM];
__device__ float g_t    [TTOT*CDIM];
__device__ float g_qkv  [TTOT*QKVC];
__device__ float g_qp   [TTOT*CDIM];
__device__ float g_kp   [TTOT*CDIM];
__device__ float g_kv   [BATCH*HNUM*RF*DHEAD];
__device__ float g_ks   [BATCH*HNUM*RF];
__device__ int   g_stab;
__device__ __nv_bfloat16 g_wh[WTOT];
__device__ __nv_bfloat16 g_wl[WTOT];
// split activations (GEMM A operands)
__device__ __nv_bfloat16 g_colh[PTOT*CDIM],  g_coll[PTOT*CDIM];
__device__ __nv_bfloat16 g_lnh [TTOT*CDIM],  g_lnl [TTOT*CDIM];
__device__ __nv_bfloat16 g_attnh[TTOT*CDIM], g_attnl[TTOT*CDIM];
__device__ __nv_bfloat16 g_hidh[TTOT*HIDD],  g_hidl[TTOT*HIDD];

__device__ __forceinline__ int   encf(float f){ int i=__float_as_int(f); return i<0 ? (i^0x7FFFFFFF) : i; }
__device__ __forceinline__ float decf(int i){ return __int_as_float(i<0 ? (i^0x7FFFFFFF) : i); }

__device__ __forceinline__ void split1(float v, __nv_bfloat16& h, __nv_bfloat16& l){
    h = __float2bfloat16(v);
    l = __float2bfloat16(v - __bfloat162float(h));
}

// ---------------- weight split ----------------
__global__ void wsplit4_k(const float* __restrict__ w,
                          __nv_bfloat16* __restrict__ hi,
                          __nv_bfloat16* __restrict__ lo, int n4){
    int i = blockIdx.x*blockDim.x + threadIdx.x;
    if (i >= n4) return;
    float4 v = ((const float4*)w)[i];
    __nv_bfloat16 hx,lx,hy,ly,hz,lz,hw,lw;
    split1(v.x,hx,lx); split1(v.y,hy,ly); split1(v.z,hz,lz); split1(v.w,hw,lw);
    __nv_bfloat162* h2 = (__nv_bfloat162*)hi;
    __nv_bfloat162* l2 = (__nv_bfloat162*)lo;
    h2[i*2]   = __halves2bfloat162(hx, hy);
    h2[i*2+1] = __halves2bfloat162(hz, hw);
    l2[i*2]   = __halves2bfloat162(lx, ly);
    l2[i*2+1] = __halves2bfloat162(lz, lw);
}

// ---------------- im2col (writes split bf16 directly) ----------------
__global__ void im2col_k(const float* __restrict__ x){
    int idx = blockIdx.x*blockDim.x + threadIdx.x;
    if (idx >= PTOT*CDIM) return;
    int p = idx / CDIM, j = idx % CDIM;
    int b = p / NPATCH, pin = p % NPATCH;
    int py = pin / 14, px = pin % 14;
    int ci = j >> 8, rem = j & 255;
    int ky = rem >> 4, kx = rem & 15;
    float v = x[((b*3 + ci)*224 + (py*16+ky))*224 + (px*16+kx)];
    __nv_bfloat16 h,l; split1(v,h,l);
    g_colh[idx] = h; g_coll[idx] = l;
}

// ---------------- assemble ----------------
__global__ void assemble_k(const float* __restrict__ cls, const float* __restrict__ pos){
    int idx = blockIdx.x*blockDim.x + threadIdx.x;
    if (idx >= TTOT*CDIM) return;
    int t = idx / CDIM, c = idx % CDIM;
    int b = t / NTOK, n = t % NTOK;
    float v = (n == 0) ? cls[c] : g_patch[(b*NPATCH + n - 1)*CDIM + c];
    g_t[idx] = v + pos[n*CDIM + c];
}

// ---------------- layernorm (writes split bf16) ----------------
__global__ void ln_k(const float* __restrict__ in, long istride,
                     const float* __restrict__ w, const float* __restrict__ bb,
                     __nv_bfloat16* __restrict__ oh, __nv_bfloat16* __restrict__ ol){
    long row = blockIdx.x;
    const float* xr = in + row*istride;
    long ro = row*(long)CDIM;
    int tid = threadIdx.x;
    float v0 = xr[tid], v1 = xr[tid+256], v2 = xr[tid+512];
    float s  = v0+v1+v2;
    float s2 = v0*v0 + v1*v1 + v2*v2;
    __shared__ float sh1[8], sh2[8], mv[2];
    #pragma unroll
    for (int o=16;o>0;o>>=1){
        s  += __shfl_down_sync(0xffffffffu, s,  o);
        s2 += __shfl_down_sync(0xffffffffu, s2, o);
    }
    if ((tid&31)==0){ sh1[tid>>5]=s; sh2[tid>>5]=s2; }
    __syncthreads();
    if (tid < 32){
        float a = (tid<8)? sh1[tid] : 0.f;
        float b2= (tid<8)? sh2[tid] : 0.f;
        #pragma unroll
        for (int o=4;o>0;o>>=1){
            a  += __shfl_down_sync(0xffffffffu, a,  o);
            b2 += __shfl_down_sync(0xffffffffu, b2, o);
        }
        if (tid==0){
            float mu = a * (1.f/CDIM);
            float var = b2 * (1.f/CDIM) - mu*mu;
            mv[0] = mu; mv[1] = rsqrtf(var + 1e-6f);
        }
    }
    __syncthreads();
    float mu = mv[0], rs = mv[1];
    __nv_bfloat16 h,l;
    float y0 = (v0-mu)*rs*w[tid]     + bb[tid];
    float y1 = (v1-mu)*rs*w[tid+256] + bb[tid+256];
    float y2 = (v2-mu)*rs*w[tid+512] + bb[tid+512];
    split1(y0,h,l); oh[ro+tid]     = h; ol[ro+tid]     = l;
    split1(y1,h,l); oh[ro+tid+256] = h; ol[ro+tid+256] = l;
    split1(y2,h,l); oh[ro+tid+512] = h; ol[ro+tid+512] = l;
}

// ---------------- performer feature maps ----------------
__global__ void phiq_k(const float* __restrict__ worf){
    int blk = blockIdx.x;
    int t = blk / HNUM, h = blk - t*HNUM;
    int m = threadIdx.x;
    __shared__ float dv[64];
    __shared__ float red[64];
    dv[m] = g_qkv[(long)t*QKVC + h*DHEAD + m];
    __syncthreads();
    red[m] = dv[m]; __syncthreads();
    #pragma unroll
    for (int o=32;o>0;o>>=1){ if (m<o) red[m]+=red[m+o]; __syncthreads(); }
    float diag = red[0] * 0.0625f;
    __syncthreads();
    float dot = 0.f;
    const float* wr = worf + m*DHEAD;
    #pragma unroll 16
    for (int d=0; d<DHEAD; d++) dot = fmaf(dv[d], wr[d], dot);
    red[m] = dot; __syncthreads();
    #pragma unroll
    for (int o=32;o>0;o>>=1){ if (m<o) red[m]=fmaxf(red[m],red[m+o]); __syncthreads(); }
    float stab = red[0];
    g_qp[(long)t*CDIM + h*DHEAD + m] = 0.35355339f*(expf(dot - diag - stab) + 1e-6f);
}

__global__ void reset_stab_k(){ g_stab = (int)0x80000000; }

__global__ void phik_k(const float* __restrict__ worf){
    int blk = blockIdx.x;
    int t = blk / HNUM, h = blk - t*HNUM;
    int m = threadIdx.x;
    __shared__ float dv[64];
    __shared__ float red[64];
    dv[m] = g_qkv[(long)t*QKVC + CDIM + h*DHEAD + m];
    __syncthreads();
    red[m] = dv[m]; __syncthreads();
    #pragma unroll
    for (int o=32;o>0;o>>=1){ if (m<o) red[m]+=red[m+o]; __syncthreads(); }
    float diag = red[0] * 0.0625f;
    __syncthreads();
    float dot = 0.f;
    const float* wr = worf + m*DHEAD;
    #pragma unroll 16
    for (int d=0; d<DHEAD; d++) dot = fmaf(dv[d], wr[d], dot);
    g_kp[(long)t*CDIM + h*DHEAD + m] = dot - diag;
    red[m] = dot; __syncthreads();
    #pragma unroll
    for (int o=32;o>0;o>>=1){ if (m<o) red[m]=fmaxf(red[m],red[m+o]); __syncthreads(); }
    if (m==0) atomicMax(&g_stab, encf(red[0]));
}

__global__ void kexp_k(){
    int idx = blockIdx.x*blockDim.x + threadIdx.x;
    if (idx >= TTOT*CDIM) return;
    float stab = decf(g_stab);
    g_kp[idx] = 0.35355339f*(expf(g_kp[idx] - stab) + 1e-6f);
}

// ---------------- kv / num ----------------
__global__ void __launch_bounds__(256) kv_k(){
    int bh = blockIdx.x;
    int b = bh / HNUM, h = bh - b*HNUM;
    __shared__ float kps[64], vs[64];
    int tid = threadIdx.x;
    int m = tid >> 2, d0 = (tid & 3) * 16;
    float acc[16];
    #pragma unroll
    for (int j=0;j<16;j++) acc[j]=0.f;
    float ksacc = 0.f;
    for (int l=0; l<NTOK; l++){
        long t = (long)b*NTOK + l;
        if (tid < 64)        kps[tid]    = g_kp [t*CDIM + h*DHEAD + tid];
        else if (tid < 128)  vs[tid-64]  = g_qkv[t*QKVC + 2*CDIM + h*DHEAD + (tid-64)];
        __syncthreads();
        float km = kps[m];
        #pragma unroll
        for (int j=0;j<16;j++) acc[j] = fmaf(km, vs[d0+j], acc[j]);
        if (tid < 64) ksacc += kps[tid];
        __syncthreads();
    }
    #pragma unroll
    for (int j=0;j<16;j++) g_kv[((long)bh*RF + m)*DHEAD + d0 + j] = acc[j];
    if (tid < 64) g_ks[bh*RF + tid] = ksacc;
}

__global__ void __launch_bounds__(256) num_k(){
    int bh = blockIdx.x;
    int b = bh / HNUM, h = bh - b*HNUM;
    __shared__ float kvs[64][65];
    __shared__ float kss[64];
    int tid = threadIdx.x;
    for (int e=tid; e<RF*DHEAD; e+=256){
        kvs[e>>6][e&63] = g_kv[(long)bh*RF*DHEAD + e];
    }
    if (tid < 64) kss[tid] = g_ks[bh*RF + tid];
    __syncthreads();
    int grp = tid >> 6, d = tid & 63;
    for (int l=grp; l<NTOK; l+=4){
        long t = (long)b*NTOK + l;
        const float* qrow = &g_qp[t*CDIM + h*DHEAD];
        float num=0.f, den=0.f;
        #pragma unroll 16
        for (int mm=0; mm<RF; mm++){
            float qv = __ldg(qrow + mm);
            num = fmaf(qv, kvs[mm][d], num);
            den = fmaf(qv, kss[mm], den);
        }
        float v = num/den;
        __nv_bfloat16 hh,ll; split1(v,hh,ll);
        long o = t*CDIM + h*DHEAD + d;
        g_attnh[o] = hh; g_attnl[o] = ll;
    }
}

// ---------------- bf16-split tensor-core NT GEMM, cp.async double-buffered ----
// C = act(Ah+Al @ (Wh+Wl)^T + bias); 3 MMA terms HH+HL+LH, fp32 accum.
// A,W both pre-split bf16 [rows][K]. CTA tile 128x128, K-chunk 32.
#define SROW 20           // u32 per smem row (16 data + 4 pad)
#define TILE_U32 2560     // 128*SROW
#define STAGE_U32 10240   // 4 tiles

__device__ __forceinline__ uint32_t smem_u32(const void* p){
    uint32_t a;
    asm("{ .reg .u64 t; cvta.to.shared.u64 t, %1; cvt.u32.u64 %0, t; }" : "=r"(a) : "l"(p));
    return a;
}
#define CP16(dst,src,sz) asm volatile("cp.async.cg.shared.global [%0],[%1],16,%2;" :: "r"(dst),"l"(src),"r"(sz))
#define CP_COMMIT()      asm volatile("cp.async.commit_group;" ::: "memory")
#define CP_WAIT0()       asm volatile("cp.async.wait_group 0;" ::: "memory")
#define CP_WAIT1()       asm volatile("cp.async.wait_group 1;" ::: "memory")

__device__ __forceinline__ void mma16(float* c, const uint32_t* a, const uint32_t* b){
    asm volatile("mma.sync.aligned.m16n8k16.row.col.f32.bf16.bf16.f32 "
        "{%0,%1,%2,%3}, {%4,%5,%6,%7}, {%8,%9}, {%0,%1,%2,%3};"
        : "+f"(c[0]), "+f"(c[1]), "+f"(c[2]), "+f"(c[3])
        : "r"(a[0]), "r"(a[1]), "r"(a[2]), "r"(a[3]), "r"(b[0]), "r"(b[1]));
}

// OMODE: 0 = f32 store, 1 = f32 store + residual, 2 = bf16 hi/lo split store
template<int ACT, int OMODE>
__global__ void __launch_bounds__(256,2) gemm_bf(
        const __nv_bfloat16* __restrict__ Ah,
        const __nv_bfloat16* __restrict__ Al, int lda,
        const __nv_bfloat16* __restrict__ Wh,
        const __nv_bfloat16* __restrict__ Wl, int ldw,
        const float* __restrict__ bias,
        float* __restrict__ Cd,
        __nv_bfloat16* __restrict__ Oh,
        __nv_bfloat16* __restrict__ Ol, int ldc,
        int Mrows, int Ncols, int K)
{
    extern __shared__ uint32_t sm[];
    uint32_t sb = smem_u32(sm);

    int tid  = threadIdx.x;
    int wid  = tid >> 5, lane = tid & 31;
    int wm   = (wid >> 2) * 64;
    int wn   = (wid & 3)  * 32;
    int row0 = blockIdx.y * 128;
    int col0 = blockIdx.x * 128;

    float acc[4][4][4];
    #pragma unroll
    for (int i=0;i<4;i++)
        #pragma unroll
        for (int j=0;j<4;j++)
            #pragma unroll
            for (int e=0;e<4;e++) acc[i][j][e]=0.f;

    // staging geometry: e=tid+256*it -> r=e>>2 (0..127), cc=e&3 (16B chunk = 8 bf16)
    const int r_   = (tid >> 2);
    const int r1_  = r_ + 64;          // second row this thread covers
    const int cc_  = (tid & 3);
    int gra0 = row0 + r_,  gra1 = row0 + r1_;
    int gnb0 = col0 + r_,  gnb1 = col0 + r1_;
    int sza0 = (gra0 < Mrows) ? 16 : 0;
    int sza1 = (gra1 < Mrows) ? 16 : 0;
    int szb0 = (gnb0 < Ncols) ? 16 : 0;
    int szb1 = (gnb1 < Ncols) ? 16 : 0;
    long aoff0 = (long)min(gra0, Mrows-1)*lda + cc_*8;
    long aoff1 = (long)min(gra1, Mrows-1)*lda + cc_*8;
    long boff0 = (long)min(gnb0, Ncols-1)*ldw + cc_*8;
    long boff1 = (long)min(gnb1, Ncols-1)*ldw + cc_*8;
    uint32_t d0 = sb + (r_ *SROW + cc_*4)*4;
    uint32_t d1 = sb + (r1_*SROW + cc_*4)*4;

    const int nchunk = K >> 5;

    // prologue: stage 0, chunk 0
    {
        CP16(d0,              Ah + aoff0,       sza0);
        CP16(d1,              Ah + aoff1,       sza1);
        CP16(d0 + TILE_U32*4, Al + aoff0,       sza0);
        CP16(d1 + TILE_U32*4, Al + aoff1,       sza1);
        CP16(d0 + 2*TILE_U32*4, Wh + boff0,     szb0);
        CP16(d1 + 2*TILE_U32*4, Wh + boff1,     szb1);
        CP16(d0 + 3*TILE_U32*4, Wl + boff0,     szb0);
        CP16(d1 + 3*TILE_U32*4, Wl + boff1,     szb1);
        CP_COMMIT();
    }

    for (int c = 0; c < nchunk; c++){
        if (c + 1 < nchunk){
            long k8 = (long)(c+1) * 4;   // 32 bf16 = 4*8
            uint32_t so = ((c+1) & 1) * STAGE_U32 * 4;
            CP16(d0 + so,               Ah + aoff0 + k8*8, sza0);
            CP16(d1 + so,               Ah + aoff1 + k8*8, sza1);
            CP16(d0 + so + TILE_U32*4,  Al + aoff0 + k8*8, sza0);
            CP16(d1 + so + TILE_U32*4,  Al + aoff1 + k8*8, sza1);
            CP16(d0 + so + 2*TILE_U32*4, Wh + boff0 + k8*8, szb0);
            CP16(d1 + so + 2*TILE_U32*4, Wh + boff1 + k8*8, szb1);
            CP16(d0 + so + 3*TILE_U32*4, Wl + boff0 + k8*8, szb0);
            CP16(d1 + so + 3*TILE_U32*4, Wl + boff1 + k8*8, szb1);
            CP_COMMIT();
            CP_WAIT1();
        } else {
            CP_WAIT0();
        }
        __syncthreads();

        const uint32_t* S   = sm + (c & 1) * STAGE_U32;
        const uint32_t* AsH = S;
        const uint32_t* AsL = S + TILE_U32;
        const uint32_t* BsH = S + 2*TILE_U32;
        const uint32_t* BsL = S + 3*TILE_U32;

        #pragma unroll
        for (int ks = 0; ks < 2; ks++){
            int kk = ks*8 + (lane & 3);
            uint32_t bH[4][2], bL[4][2];
            #pragma unroll
            for (int nt = 0; nt < 4; nt++){
                int n = wn + nt*8 + (lane >> 2);
                int o = n*SROW + kk;
                bH[nt][0] = BsH[o]; bH[nt][1] = BsH[o+4];
                bL[nt][0] = BsL[o]; bL[nt][1] = BsL[o+4];
            }
            #pragma unroll
            for (int mt = 0; mt < 4; mt++){
                int r = wm + mt*16 + (lane >> 2);
                int o0 =  r   *SROW + kk;
                int o1 = (r+8)*SROW + kk;
                uint32_t aH[4] = { AsH[o0], AsH[o1], AsH[o0+4], AsH[o1+4] };
                uint32_t aL[4] = { AsL[o0], AsL[o1], AsL[o0+4], AsL[o1+4] };
                #pragma unroll
                for (int nt = 0; nt < 4; nt++){
                    mma16(acc[mt][nt], aH, bH[nt]);
                    mma16(acc[mt][nt], aH, bL[nt]);
                    mma16(acc[mt][nt], aL, bH[nt]);
                }
            }
        }
        __syncthreads();
    }

    // epilogue
    #pragma unroll
    for (int mt=0; mt<4; mt++){
        int r0 = row0 + wm + mt*16 + (lane >> 2);
        #pragma unroll
        for (int nt=0; nt<4; nt++){
            int c0 = col0 + wn + nt*8 + (lane & 3)*2;
            #pragma unroll
            for (int e=0; e<4; e++){
                int r = r0 + (e>>1)*8;
                int c = c0 + (e&1);
                if (r >= Mrows || c >= Ncols) continue;
                float v = acc[mt][nt][e] + bias[c];
                if (ACT == 1) v = v * normcdff(v);
                long o = (long)r*ldc + c;
                if (OMODE == 0) Cd[o] = v;
                else if (OMODE == 1) Cd[o] += v;
                else {
                    __nv_bfloat16 hh,ll; split1(v,hh,ll);
                    Oh[o] = hh; Ol[o] = ll;
                }
            }
        }
    }
}

// ---------------- driver ----------------
extern "C" void kernel_launch(void* const* d_in, const int* in_sizes, int n_in,
                              void* d_out, int out_size){
    (void)in_sizes; (void)n_in; (void)out_size;
    const float* x       = (const float*)d_in[0];
    const float* patch_w = (const float*)d_in[1];
    const float* patch_b = (const float*)d_in[2];
    const float* cls     = (const float*)d_in[3];
    const float* pos     = (const float*)d_in[4];
    const float* ln1w    = (const float*)d_in[5];
    const float* ln1b    = (const float*)d_in[6];
    const float* qkvw    = (const float*)d_in[7];
    const float* qkvb    = (const float*)d_in[8];
    const float* worf    = (const float*)d_in[9];
    const float* projw   = (const float*)d_in[10];
    const float* projb   = (const float*)d_in[11];
    const float* ln2w    = (const float*)d_in[12];
    const float* ln2b    = (const float*)d_in[13];
    const float* fc1w    = (const float*)d_in[14];
    const float* fc1b    = (const float*)d_in[15];
    const float* fc2w    = (const float*)d_in[16];
    const float* fc2b    = (const float*)d_in[17];
    const float* lnfw    = (const float*)d_in[18];
    const float* lnfb    = (const float*)d_in[19];
    const float* headw   = (const float*)d_in[20];
    const float* headb   = (const float*)d_in[21];
    float* out = (float*)d_out;

    float *patchp,*tp,*qkvp,*hid_dummy=nullptr;
    __nv_bfloat16 *whp,*wlp,*colh,*coll,*lnh,*lnl,*ath,*atl,*hih,*hil;
    cudaGetSymbolAddress((void**)&patchp,g_patch);
    cudaGetSymbolAddress((void**)&tp,    g_t);
    cudaGetSymbolAddress((void**)&qkvp,  g_qkv);
    cudaGetSymbolAddress((void**)&whp,   g_wh);
    cudaGetSymbolAddress((void**)&wlp,   g_wl);
    cudaGetSymbolAddress((void**)&colh,  g_colh);
    cudaGetSymbolAddress((void**)&coll,  g_coll);
    cudaGetSymbolAddress((void**)&lnh,   g_lnh);
    cudaGetSymbolAddress((void**)&lnl,   g_lnl);
    cudaGetSymbolAddress((void**)&ath,   g_attnh);
    cudaGetSymbolAddress((void**)&atl,   g_attnl);
    cudaGetSymbolAddress((void**)&hih,   g_hidh);
    cudaGetSymbolAddress((void**)&hil,   g_hidl);

    const int SMB = STAGE_U32 * 2 * 4;   // 80KB
    cudaFuncSetAttribute(gemm_bf<0,0>, cudaFuncAttributeMaxDynamicSharedMemorySize, SMB);
    cudaFuncSetAttribute(gemm_bf<0,1>, cudaFuncAttributeMaxDynamicSharedMemorySize, SMB);
    cudaFuncSetAttribute(gemm_bf<1,2>, cudaFuncAttributeMaxDynamicSharedMemorySize, SMB);

    // ---- weight pre-split ----
    {
        auto ws = [&](const float* src, long off, long cnt){
            wsplit4_k<<<(int)((cnt/4 + 255)/256), 256>>>(src, whp+off, wlp+off, (int)(cnt/4));
        };
        ws(patch_w, WOFF_PATCH, 589824);
        ws(headw,   WOFF_HEAD,  768000);
        for (int i=0;i<LNUM;i++){
            ws(qkvw  + (long)i*QKVC*CDIM, WOFF_QKV  + (long)i*1769472, 1769472);
            ws(projw + (long)i*CDIM*CDIM, WOFF_PROJ + (long)i*589824,  589824);
            ws(fc1w  + (long)i*HIDD*CDIM, WOFF_FC1  + (long)i*2359296, 2359296);
            ws(fc2w  + (long)i*CDIM*HIDD, WOFF_FC2  + (long)i*2359296, 2359296);
        }
    }

    const int mtT = (TTOT + 127) / 128;   // 50
    const int mtP = (PTOT + 127) / 128;   // 49

    im2col_k<<<(PTOT*CDIM+255)/256, 256>>>(x);
    gemm_bf<0,0><<<dim3(CDIM/128, mtP), 256, SMB>>>(colh, coll, CDIM,
            whp+WOFF_PATCH, wlp+WOFF_PATCH, CDIM, patch_b,
            patchp, nullptr, nullptr, CDIM, PTOT, CDIM, CDIM);
    assemble_k<<<(TTOT*CDIM+255)/256, 256>>>(cls, pos);

    for (int i=0; i<LNUM; i++){
        ln_k<<<TTOT, 256>>>(tp, CDIM, ln1w + i*CDIM, ln1b + i*CDIM, lnh, lnl);
        gemm_bf<0,0><<<dim3(QKVC/128, mtT), 256, SMB>>>(lnh, lnl, CDIM,
                whp+WOFF_QKV+(long)i*1769472, wlp+WOFF_QKV+(long)i*1769472, CDIM,
                qkvb + i*QKVC, qkvp, nullptr, nullptr, QKVC, TTOT, QKVC, CDIM);
        phiq_k<<<TTOT*HNUM, 64>>>(worf + (long)i*RF*DHEAD);
        reset_stab_k<<<1,1>>>();
        phik_k<<<TTOT*HNUM, 64>>>(worf + (long)i*RF*DHEAD);
        kexp_k<<<(TTOT*CDIM+255)/256, 256>>>();
        kv_k<<<BATCH*HNUM, 256>>>();
        num_k<<<BATCH*HNUM, 256>>>();
        gemm_bf<0,1><<<dim3(CDIM/128, mtT), 256, SMB>>>(ath, atl, CDIM,
                whp+WOFF_PROJ+(long)i*589824, wlp+WOFF_PROJ+(long)i*589824, CDIM,
                projb + i*CDIM, tp, nullptr, nullptr, CDIM, TTOT, CDIM, CDIM);
        ln_k<<<TTOT, 256>>>(tp, CDIM, ln2w + i*CDIM, ln2b + i*CDIM, lnh, lnl);
        gemm_bf<1,2><<<dim3(HIDD/128, mtT), 256, SMB>>>(lnh, lnl, CDIM,
                whp+WOFF_FC1+(long)i*2359296, wlp+WOFF_FC1+(long)i*2359296, CDIM,
                fc1b + i*HIDD, nullptr, hih, hil, HIDD, TTOT, HIDD, CDIM);
        gemm_bf<0,1><<<dim3(CDIM/128, mtT), 256, SMB>>>(hih, hil, HIDD,
                whp+WOFF_FC2+(long)i*2359296, wlp+WOFF_FC2+(long)i*2359296, HIDD,
                fc2b + i*CDIM, tp, nullptr, nullptr, CDIM, TTOT, CDIM, HIDD);
    }

    ln_k<<<BATCH, 256>>>(tp, (long)NTOK*CDIM, lnfw, lnfb, lnh, lnl);
    gemm_bf<0,0><<<dim3((NCLS_+127)/128, 1), 256, SMB>>>(lnh, lnl, CDIM,
            whp+WOFF_HEAD, wlp+WOFF_HEAD, CDIM, headb,
            out, nullptr, nullptr, NCLS_, BATCH, NCLS_, CDIM);
}